// round 17
// baseline (speedup 1.0000x reference)
#include <cuda_runtime.h>

// Problem constants
#define BB   4
#define CC   16
#define HH   64
#define WW   64
#define FF   32
#define K2   9

#define TILE_W   8      // pixels per block
#define THREADS  128    // 4 warps = 4 c-quarters; each warp: all 8 px, lane=f
#define XCOLS    12     // 10 halo cols padded to 12 (16B-aligned rows)

// Repacked coefficients: [c][k][g][f] float4
//   g=0: {n0,n1,n2,n3}   g=1: {n4,n5,d0,d1}   g=2: {d2,d3,0,0}
__device__ float4 g_coef4[CC * K2 * 3 * FF];   // 221 KB (L2/L1 resident)

__device__ __forceinline__ float rcp_fast(float q) {
    float r; asm("rcp.approx.f32 %0, %1;" : "=f"(r) : "f"(q)); return r;
}
__device__ __forceinline__ float abs_bits(float v) {
    return __int_as_float(__float_as_int(v) & 0x7fffffff);
}

// ---------------------------------------------------------------------------
// Kernel 1: repack coefficients into [c][k][g][f] float4.
// Fires programmatic completion immediately: the conv grid launches and runs
// its halo prologue concurrently (PDL); conv syncs before reading g_coef4.
// ---------------------------------------------------------------------------
__global__ void repack_coefs_kernel(const float* __restrict__ nums,
                                    const float* __restrict__ denoms) {
#if __CUDA_ARCH__ >= 900
    cudaTriggerProgrammaticLaunchCompletion();
#endif
    int idx = blockIdx.x * blockDim.x + threadIdx.x;
    const int total = CC * K2 * 3 * FF;
    if (idx >= total) return;
    int f = idx & (FF - 1);
    int g = (idx >> 5) % 3;
    int k = (idx >> 5) / 3 % K2;
    int c = idx / (FF * 3 * K2);
    const float* np = nums   + (((f * CC + c) * K2) + k) * 6;
    const float* dp = denoms + (((f * CC + c) * K2) + k) * 4;
    float4 v;
    if (g == 0)      v = make_float4(np[0], np[1], np[2], np[3]);
    else if (g == 1) v = make_float4(np[4], np[5], dp[0], dp[1]);
    else             v = make_float4(dp[2], dp[3], 0.f, 0.f);
    g_coef4[idx] = v;
}

// ---------------------------------------------------------------------------
// Kernel 2: rational (Pade) conv — 10 fma-pipe ops per eval:
//   P Horner(5) + w Horner(3) + q=fma(|x|,|w|,1)(1) + acc fma(1).
//   |x| window precomputed (10 LOP3 per (c,a) serving 24 evals); per-eval
//   alu = 1 LOP3 (|w|).
//   grid  = (W/8, H, B) = (8, 64, 4) = 2048 blocks, 128 threads (4 warps)
//   -> 13.8 blocks/SM backlog keeps 7 CTAs (28 warps) resident; tail <= 7%.
//   lane = f; warp = c-quarter (4 channels), all 8 pixels.
//   Coefficients: direct __ldg each k-step; ptxas pipelines across the
//   9 unrolled k-steps per channel (no explicit double-buffer MOV churn).
//   4-way c reduction via smem, fixed order (deterministic).
// ---------------------------------------------------------------------------
__global__ __launch_bounds__(THREADS, 7)
void rational_conv_kernel(const float* __restrict__ x, float* __restrict__ out) {
    __shared__ __align__(16) float xs[CC][3][XCOLS];   // 2.25 KB halo
    __shared__ float red[3][32][9];                    // quarters 1..3, pad 9

    const int wbase = blockIdx.x * TILE_W;
    const int h     = blockIdx.y;
    const int b     = blockIdx.z;
    const int tid   = threadIdx.x;
    const int lane  = tid & 31;            // f
    const int warp  = tid >> 5;            // c-quarter 0..3

    // --- Load halo: 16 channels x 3 rows x 10 cols (wbase-1 .. wbase+8)
    //     (independent of repack output -> overlaps repack under PDL)
    for (int i = tid; i < CC * 3 * 10; i += THREADS) {
        int j  = i % 10;
        int r  = (i / 10) % 3;
        int c  = i / 30;
        int hh = h - 1 + r;
        int ww = wbase - 1 + j;
        float v = 0.0f;
        if (hh >= 0 && hh < HH && ww >= 0 && ww < WW)
            v = x[((b * CC + c) * HH + hh) * WW + ww];
        xs[c][r][j] = v;
    }
    __syncthreads();

#if __CUDA_ARCH__ >= 900
    cudaGridDependencySynchronize();   // repack stores visible before coeff reads
#endif

    float acc[8];
    #pragma unroll
    for (int i = 0; i < 8; ++i) acc[i] = 0.0f;

    const int cstart = warp * 4;
    const float4* __restrict__ cq = g_coef4 + (cstart * K2) * 3 * FF + lane;

    #pragma unroll 1
    for (int cc = 0; cc < 4; ++cc) {
        const float4* cfc = cq + cc * (K2 * 3 * FF);
        #pragma unroll
        for (int a = 0; a < 3; ++a) {
            // 10-float x window via broadcast LDS (16B-aligned row base)
            const float* xrow = &xs[cstart + cc][a][0];
            float4 xA = *reinterpret_cast<const float4*>(xrow);
            float4 xB = *reinterpret_cast<const float4*>(xrow + 4);
            float2 xC = *reinterpret_cast<const float2*>(xrow + 8);
            const float xw[10] = {xA.x, xA.y, xA.z, xA.w,
                                  xB.x, xB.y, xB.z, xB.w,
                                  xC.x, xC.y};
            // |x| window: 10 LOP3 serve 24 evals
            float xa[10];
            #pragma unroll
            for (int j = 0; j < 10; ++j) xa[j] = abs_bits(xw[j]);

            #pragma unroll
            for (int bb = 0; bb < 3; ++bb) {
                // 3 lane-strided LDG.128; ptxas pipelines these across the
                // 9 unrolled k-steps of this channel
                const float4* cp = cfc + ((a * 3 + bb) * 3) * FF;
                const float4 A  = __ldg(cp);
                const float4 Bv = __ldg(cp + FF);
                const float4 Cv = __ldg(cp + 2 * FF);
                const float n0 = A.x,  n1 = A.y,  n2 = A.z,  n3 = A.w;
                const float n4 = Bv.x, n5 = Bv.y, d0 = Bv.z, d1 = Bv.w;
                const float d2 = Cv.x, d3 = Cv.y;
                #pragma unroll
                for (int i = 0; i < 8; ++i) {
                    const float xv = xw[i + bb];
                    // P(x): Horner, 5 FMA
                    float p = fmaf(xv, n5, n4);
                    p = fmaf(xv, p, n3);
                    p = fmaf(xv, p, n2);
                    p = fmaf(xv, p, n1);
                    p = fmaf(xv, p, n0);
                    // w(x) = d0 + d1 x + d2 x^2 + d3 x^3: 3 FMA
                    float w = fmaf(xv, d3, d2);
                    w = fmaf(xv, w, d1);
                    w = fmaf(xv, w, d0);
                    // Q = 1 + |x*w| = fma(|x|, |w|, 1): 1 LOP3 + 1 FMA
                    const float q = fmaf(xa[i + bb], abs_bits(w), 1.0f);
                    acc[i] = fmaf(p, rcp_fast(q), acc[i]);
                }
            }
        }
    }

    // --- 4-way c reduction via smem, fixed order (deterministic)
    if (warp != 0) {
        #pragma unroll
        for (int i = 0; i < 8; ++i) red[warp - 1][lane][i] = acc[i];
    }
    __syncthreads();
    if (warp == 0) {
        #pragma unroll
        for (int i = 0; i < 8; ++i)
            acc[i] = ((acc[i] + red[0][lane][i]) +
                      red[1][lane][i]) + red[2][lane][i];
        float* op = out + ((b * FF + lane) * HH + h) * WW + wbase;
        *reinterpret_cast<float4*>(op)     = make_float4(acc[0], acc[1], acc[2], acc[3]);
        *reinterpret_cast<float4*>(op + 4) = make_float4(acc[4], acc[5], acc[6], acc[7]);
    }
}

// ---------------------------------------------------------------------------
// Launch: repack, then conv with Programmatic Stream Serialization so the
// conv grid launches (and runs its halo prologue) while repack finishes.
// ---------------------------------------------------------------------------
extern "C" void kernel_launch(void* const* d_in, const int* in_sizes, int n_in,
                              void* d_out, int out_size) {
    const float* x      = (const float*)d_in[0];   // (4,16,64,64)
    const float* nums   = (const float*)d_in[1];   // (32,16,3,3,6)
    const float* denoms = (const float*)d_in[2];   // (32,16,3,3,4)
    float* out = (float*)d_out;                    // (4,32,64,64)

    const int total = CC * K2 * 3 * FF;
    repack_coefs_kernel<<<(total + 255) / 256, 256>>>(nums, denoms);

    cudaLaunchConfig_t cfg = {};
    cfg.gridDim  = dim3(WW / TILE_W, HH, BB);
    cfg.blockDim = dim3(THREADS, 1, 1);
    cfg.dynamicSmemBytes = 0;
    cfg.stream = 0;
    cudaLaunchAttribute attrs[1];
    attrs[0].id = cudaLaunchAttributeProgrammaticStreamSerialization;
    attrs[0].val.programmaticStreamSerializationAllowed = 1;
    cfg.attrs = attrs;
    cfg.numAttrs = 1;
    cudaLaunchKernelEx(&cfg, rational_conv_kernel, x, out);
}